// round 15
// baseline (speedup 1.0000x reference)
#include <cuda_runtime.h>
#include <cuda_fp16.h>
#include <cstdint>

#define B_    2048
#define E_    16
#define H_    1024
#define M_    (B_ * E_)          // 32768
#define NH    8
#define HD    128
#define MTOT  (M_ * H_)          // 33,554,432

// ---------------- scratch (device globals; no allocation allowed) ----------
__device__ float   g_comm[MTOT];           // residual (comm), fp32
__device__ __half  g_xn[MTOT];             // layernormed comm, fp16
__device__ __half  g_wh[4 * H_ * H_];      // wq|wk|wv|wo in fp16
__device__ __half  g_q[MTOT];
__device__ __half  g_k[MTOT];
__device__ __half  g_v[MTOT];
__device__ __half  g_att[MTOT];            // attention output, fp16
__device__ float   g_co[MTOT];             // comm_out, fp32

// ---------------- small PTX helpers ----------------------------------------
__device__ __forceinline__ void ldmatrix_x4(uint32_t* r, uint32_t addr) {
    asm volatile("ldmatrix.sync.aligned.m8n8.x4.shared.b16 {%0,%1,%2,%3}, [%4];\n"
                 : "=r"(r[0]), "=r"(r[1]), "=r"(r[2]), "=r"(r[3]) : "r"(addr));
}
__device__ __forceinline__ void ldmatrix_x2(uint32_t* r, uint32_t addr) {
    asm volatile("ldmatrix.sync.aligned.m8n8.x2.shared.b16 {%0,%1}, [%2];\n"
                 : "=r"(r[0]), "=r"(r[1]) : "r"(addr));
}
__device__ __forceinline__ void ldmatrix_x2_trans(uint32_t* r, uint32_t addr) {
    asm volatile("ldmatrix.sync.aligned.m8n8.x2.trans.shared.b16 {%0,%1}, [%2];\n"
                 : "=r"(r[0]), "=r"(r[1]) : "r"(addr));
}
// fp32-acc mma (attention)
__device__ __forceinline__ void mma16816(float* d, const uint32_t* a, const uint32_t* b) {
    asm volatile("mma.sync.aligned.m16n8k16.row.col.f32.f16.f16.f32 "
                 "{%0,%1,%2,%3}, {%4,%5,%6,%7}, {%8,%9}, {%0,%1,%2,%3};\n"
                 : "+f"(d[0]), "+f"(d[1]), "+f"(d[2]), "+f"(d[3])
                 : "r"(a[0]), "r"(a[1]), "r"(a[2]), "r"(a[3]), "r"(b[0]), "r"(b[1]));
}
// fp16-acc mma (GEMM mainloop): d = 2 regs of packed half2
__device__ __forceinline__ void mma16816h(uint32_t* d, const uint32_t* a, const uint32_t* b) {
    asm volatile("mma.sync.aligned.m16n8k16.row.col.f16.f16.f16.f16 "
                 "{%0,%1}, {%2,%3,%4,%5}, {%6,%7}, {%0,%1};\n"
                 : "+r"(d[0]), "+r"(d[1])
                 : "r"(a[0]), "r"(a[1]), "r"(a[2]), "r"(a[3]), "r"(b[0]), "r"(b[1]));
}
__device__ __forceinline__ void cp_async16(uint32_t dst, const void* src) {
    asm volatile("cp.async.cg.shared.global [%0], [%1], 16;\n" :: "r"(dst), "l"(src));
}
__device__ __forceinline__ void cp_commit() {
    asm volatile("cp.async.commit_group;\n" ::: "memory");
}
template <int N> __device__ __forceinline__ void cp_wait() {
    asm volatile("cp.async.wait_group %0;\n" :: "n"(N) : "memory");
}

// ---------------- kernel 1: weights fp32 -> fp16 ---------------------------
__global__ void __launch_bounds__(256) wconv_kernel(
    const float* __restrict__ wq, const float* __restrict__ wk,
    const float* __restrict__ wv, const float* __restrict__ wo) {
    int i = blockIdx.x * 256 + threadIdx.x;
    int seg = i >> 18;
    const float* s = (seg == 0) ? wq : (seg == 1) ? wk : (seg == 2) ? wv : wo;
    float4 f = ((const float4*)s)[i & 0x3FFFF];
    ((__half2*)g_wh)[2 * i]     = __floats2half2_rn(f.x, f.y);
    ((__half2*)g_wh)[2 * i + 1] = __floats2half2_rn(f.z, f.w);
}

// ---------------- kernel 2: chain comm + layernorm -------------------------
__global__ void __launch_bounds__(256) comm_ln_kernel(
    const float* __restrict__ x, const float* __restrict__ ln_g,
    const float* __restrict__ ln_b) {
    const int m = blockIdx.x;
    const int e = m & 15;
    const int t = threadIdx.x;

    float4 a = make_float4(0.f, 0.f, 0.f, 0.f);
    float4 b = make_float4(0.f, 0.f, 0.f, 0.f);
    if (e > 0)  a = ((const float4*)(x + (size_t)(m - 1) * H_))[t];
    if (e < 15) b = ((const float4*)(x + (size_t)(m + 1) * H_))[t];
    float c0 = 0.5f * (a.x + b.x), c1 = 0.5f * (a.y + b.y);
    float c2 = 0.5f * (a.z + b.z), c3 = 0.5f * (a.w + b.w);

    float s1 = c0 + c1 + c2 + c3;
    float s2 = c0 * c0 + c1 * c1 + c2 * c2 + c3 * c3;

    __shared__ float red[16];
    #pragma unroll
    for (int o = 16; o; o >>= 1) {
        s1 += __shfl_xor_sync(0xffffffffu, s1, o);
        s2 += __shfl_xor_sync(0xffffffffu, s2, o);
    }
    int w = t >> 5;
    if ((t & 31) == 0) { red[w] = s1; red[8 + w] = s2; }
    __syncthreads();
    if (t < 32) {
        s1 = (t < 8) ? red[t] : 0.f;
        s2 = (t < 8) ? red[8 + t] : 0.f;
        #pragma unroll
        for (int o = 4; o; o >>= 1) {
            s1 += __shfl_xor_sync(0xffffffffu, s1, o);
            s2 += __shfl_xor_sync(0xffffffffu, s2, o);
        }
        if (t == 0) { red[0] = s1; red[8] = s2; }
    }
    __syncthreads();
    s1 = red[0]; s2 = red[8];

    const float inv = 1.f / (float)H_;
    float mu = s1 * inv;
    float var = s2 * inv - mu * mu;
    float rstd = rsqrtf(var + 1e-5f);

    float4 g4 = ((const float4*)ln_g)[t];
    float4 b4 = ((const float4*)ln_b)[t];
    ((float4*)(g_comm + (size_t)m * H_))[t] = make_float4(c0, c1, c2, c3);

    float n0 = (c0 - mu) * rstd * g4.x + b4.x;
    float n1 = (c1 - mu) * rstd * g4.y + b4.y;
    float n2 = (c2 - mu) * rstd * g4.z + b4.z;
    float n3 = (c3 - mu) * rstd * g4.w + b4.w;
    __half2 h01 = __floats2half2_rn(n0, n1);
    __half2 h23 = __floats2half2_rn(n2, n3);
    uint2 pk;
    pk.x = *(uint32_t*)&h01;
    pk.y = *(uint32_t*)&h23;
    ((uint2*)(g_xn + (size_t)m * H_))[t] = pk;
}

// ---------------- GEMM: [M,1024] x [1024,1024]^T, fp16-acc mma.sync --------
// CTA tile 128x128, 512 threads = 16 warps of 32x32 tiles, K chunk 32,
// 3-stage dual-sync pipeline. <=64 regs -> 2 CTAs/SM = 32 warps/SM.
#define LDSH        40                       // 32 + 8 halves pad (80B rows)
#define MAT_BYTES   (128 * LDSH * 2)         // 10240 B per matrix per stage
#define STG_BYTES   (2 * MAT_BYTES)          // 20480 B per stage (A + B)
#define NSTAGE      3
#define GEMM_SMEM   (NSTAGE * STG_BYTES)     // 61440 B

template <bool WO>
__device__ __forceinline__ void gemm_body(
    const __half* __restrict__ A, const __half* __restrict__ W,
    const float* __restrict__ bias, __half* __restrict__ outh,
    float* __restrict__ outf, const float* __restrict__ resid) {
    extern __shared__ __align__(16) char dsm[];
    const uint32_t sbase = (uint32_t)__cvta_generic_to_shared(dsm);

    const int t = threadIdx.x;
    const int bm = blockIdx.y << 7;
    const int bn = blockIdx.x << 7;
    const int lr = t >> 2;              // 0..127
    const int lc = (t & 3) << 3;        // 0,8,16,24 (halves)
    const __half* Ag = A + (size_t)(bm + lr) * 1024 + lc;
    const __half* Bg = W + (size_t)(bn + lr) * 1024 + lc;

    uint32_t acc[2][4][2];              // fp16x2 accumulators (16 regs)
    #pragma unroll
    for (int i = 0; i < 2; i++)
        #pragma unroll
        for (int j = 0; j < 4; j++) { acc[i][j][0] = 0u; acc[i][j][1] = 0u; }

    const int lane = t & 31, w = t >> 5;
    const int wm = (w >> 2) * 32;       // 0,32,64,96
    const int wn = (w & 3) * 32;        // 0,32,64,96

    const uint32_t woff = (uint32_t)(lr * LDSH + lc) * 2;

    auto issue = [&](int kt, int s) {
        uint32_t da = sbase + s * STG_BYTES + woff;
        const __half* a0 = Ag + kt * 32;
        const __half* b0 = Bg + kt * 32;
        cp_async16(da,             a0);
        cp_async16(da + MAT_BYTES, b0);
    };

    issue(0, 0); cp_commit();
    issue(1, 1); cp_commit();
    issue(2, 2); cp_commit();

    #pragma unroll 1
    for (int kt = 0; kt < 32; kt++) {
        const int s = kt % NSTAGE;
        cp_wait<NSTAGE - 1>();
        __syncthreads();
        const uint32_t aB = sbase + s * STG_BYTES;
        const uint32_t bB = aB + MAT_BYTES;
        #pragma unroll
        for (int kk = 0; kk < 2; kk++) {
            uint32_t af[2][4], bf[4][2];
            #pragma unroll
            for (int mt = 0; mt < 2; mt++) {
                int row = wm + mt * 16 + (lane & 15);
                int col = kk * 16 + ((lane >> 4) << 3);
                ldmatrix_x4(af[mt], aB + (uint32_t)(row * LDSH + col) * 2);
            }
            #pragma unroll
            for (int nt = 0; nt < 4; nt++) {
                int row = wn + nt * 8 + (lane & 7);
                int col = kk * 16 + (((lane >> 3) & 1) << 3);
                ldmatrix_x2(bf[nt], bB + (uint32_t)(row * LDSH + col) * 2);
            }
            #pragma unroll
            for (int mt = 0; mt < 2; mt++)
                #pragma unroll
                for (int nt = 0; nt < 4; nt++)
                    mma16816h(acc[mt][nt], af[mt], bf[nt]);
        }
        __syncthreads();
        if (kt + NSTAGE < 32) issue(kt + NSTAGE, s);
        cp_commit();                       // empty group ok — keeps count aligned
    }

    const int gid = lane >> 2, tid4 = lane & 3;
    #pragma unroll
    for (int mt = 0; mt < 2; mt++) {
        #pragma unroll
        for (int nt = 0; nt < 4; nt++) {
            int row = bm + wm + mt * 16 + gid;
            int col = bn + wn + nt * 8 + tid4 * 2;
            float b0 = bias[col], b1 = bias[col + 1];
            __half2 h0 = *(__half2*)&acc[mt][nt][0];   // row gid
            __half2 h1 = *(__half2*)&acc[mt][nt][1];   // row gid+8
            float a0 = __half2float(h0.x), a1 = __half2float(h0.y);
            float a2 = __half2float(h1.x), a3 = __half2float(h1.y);
            if (!WO) {
                *(__half2*)(outh + (size_t)row * 1024 + col) =
                    __floats2half2_rn(a0 + b0, a1 + b1);
                *(__half2*)(outh + (size_t)(row + 8) * 1024 + col) =
                    __floats2half2_rn(a2 + b0, a3 + b1);
            } else {
                float2 r0 = *(const float2*)(resid + (size_t)row * 1024 + col);
                float2 r1 = *(const float2*)(resid + (size_t)(row + 8) * 1024 + col);
                *(float2*)(outf + (size_t)row * 1024 + col) =
                    make_float2(a0 + b0 + r0.x, a1 + b1 + r0.y);
                *(float2*)(outf + (size_t)(row + 8) * 1024 + col) =
                    make_float2(a2 + b0 + r1.x, a3 + b1 + r1.y);
            }
        }
    }
}

__global__ void __launch_bounds__(512, 2) gemm_qkv_kernel(
    const float* __restrict__ bq, const float* __restrict__ bk,
    const float* __restrict__ bv) {
    int z = blockIdx.z;
    const __half* W = g_wh + (size_t)z * (H_ * H_);
    const float* bias = (z == 0) ? bq : (z == 1) ? bk : bv;
    __half* out = (z == 0) ? g_q : (z == 1) ? g_k : g_v;
    gemm_body<false>(g_xn, W, bias, out, nullptr, nullptr);
}

__global__ void __launch_bounds__(512, 2) gemm_wo_kernel(const float* __restrict__ bo) {
    gemm_body<true>(g_att, g_wh + (size_t)3 * H_ * H_, bo, nullptr, g_co, g_comm);
}

// ---------------- kernel 4: attention, mma.sync flash pattern --------------
// Block = (b, 4 heads), 128 threads; warp w handles head hq*4+w.
__global__ void __launch_bounds__(128) attn_kernel() {
    const int blk = blockIdx.x;          // b*2 + hq
    const int b = blk >> 1, hq = blk & 1;
    const int tid = threadIdx.x;
    const int w = tid >> 5, lane = tid & 31;
    const int head = hq * 4 + w;

    __shared__ __align__(16) __half sq[4][16][136];
    __shared__ __align__(16) __half sk[4][16][136];
    __shared__ __align__(16) __half sv[4][16][136];

    const size_t base = (size_t)(b * 16) * 1024 + head * 128;

    // load q/k/v for this head: 16 rows x 128 halves = 256 uint4 chunks
    #pragma unroll
    for (int i = lane; i < 256; i += 32) {
        int r = i >> 4, c = (i & 15) * 8;
        *(uint4*)&sq[w][r][c] = *(const uint4*)(g_q + base + (size_t)r * 1024 + c);
        *(uint4*)&sk[w][r][c] = *(const uint4*)(g_k + base + (size_t)r * 1024 + c);
        *(uint4*)&sv[w][r][c] = *(const uint4*)(g_v + base + (size_t)r * 1024 + c);
    }
    __syncwarp();

    // ---- QK^T: scores 16x16 in acc0 (cols 0-7) + acc1 (cols 8-15) ----
    float acc0[4] = {0.f, 0.f, 0.f, 0.f};
    float acc1[4] = {0.f, 0.f, 0.f, 0.f};
    #pragma unroll
    for (int kc = 0; kc < 8; kc++) {
        uint32_t a[4];
        ldmatrix_x4(a, (uint32_t)__cvta_generic_to_shared(
            &sq[w][lane & 15][kc * 16 + ((lane >> 4) << 3)]));
        uint32_t tb[4];
        int mi = lane >> 3;
        ldmatrix_x4(tb, (uint32_t)__cvta_generic_to_shared(
            &sk[w][(mi & 1) * 8 + (lane & 7)][kc * 16 + ((mi >> 1) << 3)]));
        uint32_t b0[2] = {tb[0], tb[2]};
        uint32_t b1[2] = {tb[1], tb[3]};
        mma16816(acc0, a, b0);
        mma16816(acc1, a, b1);
    }

    // ---- softmax in registers ----
    const float scale = 0.0883883476483184f;   // 1/sqrt(128)
    float ga0 = acc0[0] * scale, ga1 = acc0[1] * scale;
    float ga2 = acc1[0] * scale, ga3 = acc1[1] * scale;
    float hb0 = acc0[2] * scale, hb1 = acc0[3] * scale;
    float hb2 = acc1[2] * scale, hb3 = acc1[3] * scale;

    float mxg = fmaxf(fmaxf(ga0, ga1), fmaxf(ga2, ga3));
    float mxh = fmaxf(fmaxf(hb0, hb1), fmaxf(hb2, hb3));
    #pragma unroll
    for (int o = 1; o < 4; o <<= 1) {
        mxg = fmaxf(mxg, __shfl_xor_sync(0xffffffffu, mxg, o, 4));
        mxh = fmaxf(mxh, __shfl_xor_sync(0xffffffffu, mxh, o, 4));
    }
    ga0 = expf(ga0 - mxg); ga1 = expf(ga1 - mxg);
    ga2 = expf(ga2 - mxg); ga3 = expf(ga3 - mxg);
    hb0 = expf(hb0 - mxh); hb1 = expf(hb1 - mxh);
    hb2 = expf(hb2 - mxh); hb3 = expf(hb3 - mxh);
    float sg = ga0 + ga1 + ga2 + ga3;
    float sh = hb0 + hb1 + hb2 + hb3;
    #pragma unroll
    for (int o = 1; o < 4; o <<= 1) {
        sg += __shfl_xor_sync(0xffffffffu, sg, o, 4);
        sh += __shfl_xor_sync(0xffffffffu, sh, o, 4);
    }
    float ig = 1.f / sg, ih = 1.f / sh;
    ga0 *= ig; ga1 *= ig; ga2 *= ig; ga3 *= ig;
    hb0 *= ih; hb1 *= ih; hb2 *= ih; hb3 *= ih;

    // ---- pack P into A-frag layout (m16k16): acc layout == A layout ----
    uint32_t pa[4];
    __half2 t01;
    t01 = __floats2half2_rn(ga0, ga1); pa[0] = *(uint32_t*)&t01;
    t01 = __floats2half2_rn(hb0, hb1); pa[1] = *(uint32_t*)&t01;
    t01 = __floats2half2_rn(ga2, ga3); pa[2] = *(uint32_t*)&t01;
    t01 = __floats2half2_rn(hb2, hb3); pa[3] = *(uint32_t*)&t01;

    // ---- P @ V: 16 n-tiles over 128 dims ----
    float o[16][4];
    #pragma unroll
    for (int nt = 0; nt < 16; nt++) {
        o[nt][0] = o[nt][1] = o[nt][2] = o[nt][3] = 0.f;
        uint32_t bv2[2];
        ldmatrix_x2_trans(bv2, (uint32_t)__cvta_generic_to_shared(
            &sv[w][lane & 15][nt * 8]));
        mma16816(o[nt], pa, bv2);
    }

    // ---- stage O into sq[w], then coalesced store ----
    const int g = lane >> 2, t4 = lane & 3;
    #pragma unroll
    for (int nt = 0; nt < 16; nt++) {
        *(__half2*)&sq[w][g][nt * 8 + 2 * t4]     = __floats2half2_rn(o[nt][0], o[nt][1]);
        *(__half2*)&sq[w][g + 8][nt * 8 + 2 * t4] = __floats2half2_rn(o[nt][2], o[nt][3]);
    }
    __syncwarp();
    #pragma unroll
    for (int i = lane; i < 256; i += 32) {
        int r = i >> 4, c = (i & 15) * 8;
        *(uint4*)(g_att + base + (size_t)r * 1024 + c) = *(uint4*)&sq[w][r][c];
    }
}

// ---------------- kernel 6: gate + final blend -----------------------------
__global__ void __launch_bounds__(256) gate_kernel(
    const float* __restrict__ x, const float* __restrict__ wg,
    const float* __restrict__ bg, float* __restrict__ out) {
    const int m = blockIdx.x;
    const int t = threadIdx.x;

    float4 xv = ((const float4*)(x + (size_t)m * H_))[t];
    float4 cv = ((const float4*)(g_co + (size_t)m * H_))[t];
    float4 w1 = ((const float4*)wg)[t];
    float4 w2 = ((const float4*)(wg + H_))[t];

    float s = xv.x * w1.x + xv.y * w1.y + xv.z * w1.z + xv.w * w1.w
            + cv.x * w2.x + cv.y * w2.y + cv.z * w2.z + cv.w * w2.w;

    __shared__ float red[8];
    #pragma unroll
    for (int o = 16; o; o >>= 1) s += __shfl_xor_sync(0xffffffffu, s, o);
    int w = t >> 5;
    if ((t & 31) == 0) red[w] = s;
    __syncthreads();
    if (t < 32) {
        s = (t < 8) ? red[t] : 0.f;
        #pragma unroll
        for (int o = 4; o; o >>= 1) s += __shfl_xor_sync(0xffffffffu, s, o);
        if (t == 0) red[0] = s;
    }
    __syncthreads();
    s = red[0];

    float g = 1.f / (1.f + expf(-(s + bg[0])));
    float4 o4;
    o4.x = g * cv.x + (1.f - g) * xv.x;
    o4.y = g * cv.y + (1.f - g) * xv.y;
    o4.z = g * cv.z + (1.f - g) * xv.z;
    o4.w = g * cv.w + (1.f - g) * xv.w;
    ((float4*)(out + (size_t)m * H_))[t] = o4;
}

// ---------------- launch ----------------------------------------------------
extern "C" void kernel_launch(void* const* d_in, const int* in_sizes, int n_in,
                              void* d_out, int out_size) {
    const float* x    = (const float*)d_in[0];
    const float* ln_g = (const float*)d_in[1];
    const float* ln_b = (const float*)d_in[2];
    const float* wq   = (const float*)d_in[3];
    const float* bq   = (const float*)d_in[4];
    const float* wk   = (const float*)d_in[5];
    const float* bk   = (const float*)d_in[6];
    const float* wv   = (const float*)d_in[7];
    const float* bv   = (const float*)d_in[8];
    const float* wo   = (const float*)d_in[9];
    const float* bo   = (const float*)d_in[10];
    const float* wg   = (const float*)d_in[11];
    const float* bg   = (const float*)d_in[12];
    float* out = (float*)d_out;

    static bool attr_done = false;
    if (!attr_done) {
        cudaFuncSetAttribute((const void*)gemm_qkv_kernel,
                             cudaFuncAttributeMaxDynamicSharedMemorySize, GEMM_SMEM);
        cudaFuncSetAttribute((const void*)gemm_wo_kernel,
                             cudaFuncAttributeMaxDynamicSharedMemorySize, GEMM_SMEM);
        attr_done = true;
    }

    wconv_kernel<<<4096, 256>>>(wq, wk, wv, wo);
    comm_ln_kernel<<<M_, 256>>>(x, ln_g, ln_b);
    gemm_qkv_kernel<<<dim3(8, 256, 3), 512, GEMM_SMEM>>>(bq, bk, bv);
    attn_kernel<<<B_ * 2, 128>>>();
    gemm_wo_kernel<<<dim3(8, 256, 1), 512, GEMM_SMEM>>>(bo);
    gate_kernel<<<M_, 256>>>(x, wg, bg, out);
}

// round 17
// speedup vs baseline: 1.1375x; 1.1375x over previous
#include <cuda_runtime.h>
#include <cuda_fp16.h>
#include <cstdint>

#define B_    2048
#define E_    16
#define H_    1024
#define M_    (B_ * E_)          // 32768
#define NH    8
#define HD    128
#define MTOT  (M_ * H_)          // 33,554,432

// ---------------- scratch (device globals; no allocation allowed) ----------
__device__ float   g_comm[MTOT];           // residual (comm), fp32
__device__ __half  g_xn[MTOT];             // layernormed comm, fp16
__device__ __half  g_wh[4 * H_ * H_];      // wq|wk|wv|wo in fp16
__device__ __half  g_q[MTOT];
__device__ __half  g_k[MTOT];
__device__ __half  g_v[MTOT];
__device__ __half  g_att[MTOT];            // attention output, fp16
__device__ float   g_co[MTOT];             // comm_out, fp32

// ---------------- small PTX helpers ----------------------------------------
__device__ __forceinline__ void ldmatrix_x4(uint32_t* r, uint32_t addr) {
    asm volatile("ldmatrix.sync.aligned.m8n8.x4.shared.b16 {%0,%1,%2,%3}, [%4];\n"
                 : "=r"(r[0]), "=r"(r[1]), "=r"(r[2]), "=r"(r[3]) : "r"(addr));
}
__device__ __forceinline__ void ldmatrix_x2(uint32_t* r, uint32_t addr) {
    asm volatile("ldmatrix.sync.aligned.m8n8.x2.shared.b16 {%0,%1}, [%2];\n"
                 : "=r"(r[0]), "=r"(r[1]) : "r"(addr));
}
__device__ __forceinline__ void ldmatrix_x2_trans(uint32_t* r, uint32_t addr) {
    asm volatile("ldmatrix.sync.aligned.m8n8.x2.trans.shared.b16 {%0,%1}, [%2];\n"
                 : "=r"(r[0]), "=r"(r[1]) : "r"(addr));
}
// fp32-acc mma (attention QK^T)
__device__ __forceinline__ void mma16816(float* d, const uint32_t* a, const uint32_t* b) {
    asm volatile("mma.sync.aligned.m16n8k16.row.col.f32.f16.f16.f32 "
                 "{%0,%1,%2,%3}, {%4,%5,%6,%7}, {%8,%9}, {%0,%1,%2,%3};\n"
                 : "+f"(d[0]), "+f"(d[1]), "+f"(d[2]), "+f"(d[3])
                 : "r"(a[0]), "r"(a[1]), "r"(a[2]), "r"(a[3]), "r"(b[0]), "r"(b[1]));
}
// fp16-acc mma (GEMM mainloop + attention PV)
__device__ __forceinline__ void mma16816h(uint32_t* d, const uint32_t* a, const uint32_t* b) {
    asm volatile("mma.sync.aligned.m16n8k16.row.col.f16.f16.f16.f16 "
                 "{%0,%1}, {%2,%3,%4,%5}, {%6,%7}, {%0,%1};\n"
                 : "+r"(d[0]), "+r"(d[1])
                 : "r"(a[0]), "r"(a[1]), "r"(a[2]), "r"(a[3]), "r"(b[0]), "r"(b[1]));
}
__device__ __forceinline__ void cp_async16(uint32_t dst, const void* src) {
    asm volatile("cp.async.cg.shared.global [%0], [%1], 16;\n" :: "r"(dst), "l"(src));
}
__device__ __forceinline__ void cp_commit() {
    asm volatile("cp.async.commit_group;\n" ::: "memory");
}
template <int N> __device__ __forceinline__ void cp_wait() {
    asm volatile("cp.async.wait_group %0;\n" :: "n"(N) : "memory");
}

// ---------------- kernel 1: weights fp32 -> fp16 ---------------------------
__global__ void __launch_bounds__(256) wconv_kernel(
    const float* __restrict__ wq, const float* __restrict__ wk,
    const float* __restrict__ wv, const float* __restrict__ wo) {
    int i = blockIdx.x * 256 + threadIdx.x;
    int seg = i >> 18;
    const float* s = (seg == 0) ? wq : (seg == 1) ? wk : (seg == 2) ? wv : wo;
    float4 f = ((const float4*)s)[i & 0x3FFFF];
    ((__half2*)g_wh)[2 * i]     = __floats2half2_rn(f.x, f.y);
    ((__half2*)g_wh)[2 * i + 1] = __floats2half2_rn(f.z, f.w);
}

// ---------------- kernel 2: chain comm + layernorm -------------------------
__global__ void __launch_bounds__(256) comm_ln_kernel(
    const float* __restrict__ x, const float* __restrict__ ln_g,
    const float* __restrict__ ln_b) {
    const int m = blockIdx.x;
    const int e = m & 15;
    const int t = threadIdx.x;

    float4 a = make_float4(0.f, 0.f, 0.f, 0.f);
    float4 b = make_float4(0.f, 0.f, 0.f, 0.f);
    if (e > 0)  a = ((const float4*)(x + (size_t)(m - 1) * H_))[t];
    if (e < 15) b = ((const float4*)(x + (size_t)(m + 1) * H_))[t];
    float c0 = 0.5f * (a.x + b.x), c1 = 0.5f * (a.y + b.y);
    float c2 = 0.5f * (a.z + b.z), c3 = 0.5f * (a.w + b.w);

    float s1 = c0 + c1 + c2 + c3;
    float s2 = c0 * c0 + c1 * c1 + c2 * c2 + c3 * c3;

    __shared__ float red[16];
    #pragma unroll
    for (int o = 16; o; o >>= 1) {
        s1 += __shfl_xor_sync(0xffffffffu, s1, o);
        s2 += __shfl_xor_sync(0xffffffffu, s2, o);
    }
    int w = t >> 5;
    if ((t & 31) == 0) { red[w] = s1; red[8 + w] = s2; }
    __syncthreads();
    if (t < 32) {
        s1 = (t < 8) ? red[t] : 0.f;
        s2 = (t < 8) ? red[8 + t] : 0.f;
        #pragma unroll
        for (int o = 4; o; o >>= 1) {
            s1 += __shfl_xor_sync(0xffffffffu, s1, o);
            s2 += __shfl_xor_sync(0xffffffffu, s2, o);
        }
        if (t == 0) { red[0] = s1; red[8] = s2; }
    }
    __syncthreads();
    s1 = red[0]; s2 = red[8];

    const float inv = 1.f / (float)H_;
    float mu = s1 * inv;
    float var = s2 * inv - mu * mu;
    float rstd = rsqrtf(var + 1e-5f);

    float4 g4 = ((const float4*)ln_g)[t];
    float4 b4 = ((const float4*)ln_b)[t];
    ((float4*)(g_comm + (size_t)m * H_))[t] = make_float4(c0, c1, c2, c3);

    float n0 = (c0 - mu) * rstd * g4.x + b4.x;
    float n1 = (c1 - mu) * rstd * g4.y + b4.y;
    float n2 = (c2 - mu) * rstd * g4.z + b4.z;
    float n3 = (c3 - mu) * rstd * g4.w + b4.w;
    __half2 h01 = __floats2half2_rn(n0, n1);
    __half2 h23 = __floats2half2_rn(n2, n3);
    uint2 pk;
    pk.x = *(uint32_t*)&h01;
    pk.y = *(uint32_t*)&h23;
    ((uint2*)(g_xn + (size_t)m * H_))[t] = pk;
}

// ---------------- GEMM: [M,1024] x [1024,1024]^T, fp16-acc mma.sync --------
// CTA tile 128x128, 64x32 warp tile, K chunk 32, 3-stage dual-sync pipeline,
// fp16 accumulators -> ~85 regs -> 3 CTAs/SM (24 warps/SM).  [R11 optimum]
#define LDSH        40                       // 32 + 8 halves pad (80B rows)
#define MAT_BYTES   (128 * LDSH * 2)         // 10240 B per matrix per stage
#define STG_BYTES   (2 * MAT_BYTES)          // 20480 B per stage (A + B)
#define NSTAGE      3
#define GEMM_SMEM   (NSTAGE * STG_BYTES)     // 61440 B

template <bool WO>
__device__ __forceinline__ void gemm_body(
    const __half* __restrict__ A, const __half* __restrict__ W,
    const float* __restrict__ bias, __half* __restrict__ outh,
    float* __restrict__ outf, const float* __restrict__ resid) {
    extern __shared__ __align__(16) char dsm[];
    const uint32_t sbase = (uint32_t)__cvta_generic_to_shared(dsm);

    const int t = threadIdx.x;
    const int bm = blockIdx.y << 7;
    const int bn = blockIdx.x << 7;
    const int lr = t >> 2;              // 0..63
    const int lc = (t & 3) << 3;        // 0,8,16,24 (halves)
    const __half* Ag = A + (size_t)(bm + lr) * 1024 + lc;
    const __half* Bg = W + (size_t)(bn + lr) * 1024 + lc;

    uint32_t acc[4][4][2];              // fp16x2 accumulators
    #pragma unroll
    for (int i = 0; i < 4; i++)
        #pragma unroll
        for (int j = 0; j < 4; j++) { acc[i][j][0] = 0u; acc[i][j][1] = 0u; }

    const int lane = t & 31, w = t >> 5;
    const int wm = (w >> 2) * 64;
    const int wn = (w & 3) * 32;

    const uint32_t woff = (uint32_t)(lr * LDSH + lc) * 2;

    auto issue = [&](int kt, int s) {
        uint32_t da = sbase + s * STG_BYTES + woff;
        uint32_t db = da + MAT_BYTES;
        const __half* a0 = Ag + kt * 32;
        const __half* b0 = Bg + kt * 32;
        cp_async16(da,                     a0);
        cp_async16(da + 64 * LDSH * 2,     a0 + 64 * 1024);
        cp_async16(db,                     b0);
        cp_async16(db + 64 * LDSH * 2,     b0 + 64 * 1024);
    };

    issue(0, 0); cp_commit();
    issue(1, 1); cp_commit();
    issue(2, 2); cp_commit();

    #pragma unroll 1
    for (int kt = 0; kt < 32; kt++) {
        const int s = kt % NSTAGE;
        cp_wait<NSTAGE - 1>();
        __syncthreads();
        const uint32_t aB = sbase + s * STG_BYTES;
        const uint32_t bB = aB + MAT_BYTES;
        #pragma unroll
        for (int kk = 0; kk < 2; kk++) {
            uint32_t af[4][4], bf[4][2];
            #pragma unroll
            for (int mt = 0; mt < 4; mt++) {
                int row = wm + mt * 16 + (lane & 15);
                int col = kk * 16 + ((lane >> 4) << 3);
                ldmatrix_x4(af[mt], aB + (uint32_t)(row * LDSH + col) * 2);
            }
            #pragma unroll
            for (int nt = 0; nt < 4; nt++) {
                int row = wn + nt * 8 + (lane & 7);
                int col = kk * 16 + (((lane >> 3) & 1) << 3);
                ldmatrix_x2(bf[nt], bB + (uint32_t)(row * LDSH + col) * 2);
            }
            #pragma unroll
            for (int mt = 0; mt < 4; mt++)
                #pragma unroll
                for (int nt = 0; nt < 4; nt++)
                    mma16816h(acc[mt][nt], af[mt], bf[nt]);
        }
        __syncthreads();
        if (kt + NSTAGE < 32) issue(kt + NSTAGE, s);
        cp_commit();                       // empty group ok — keeps count aligned
    }

    const int gid = lane >> 2, tid4 = lane & 3;
    #pragma unroll
    for (int mt = 0; mt < 4; mt++) {
        #pragma unroll
        for (int nt = 0; nt < 4; nt++) {
            int row = bm + wm + mt * 16 + gid;
            int col = bn + wn + nt * 8 + tid4 * 2;
            float b0 = bias[col], b1 = bias[col + 1];
            __half2 h0 = *(__half2*)&acc[mt][nt][0];   // row gid
            __half2 h1 = *(__half2*)&acc[mt][nt][1];   // row gid+8
            float a0 = __half2float(h0.x), a1 = __half2float(h0.y);
            float a2 = __half2float(h1.x), a3 = __half2float(h1.y);
            if (!WO) {
                *(__half2*)(outh + (size_t)row * 1024 + col) =
                    __floats2half2_rn(a0 + b0, a1 + b1);
                *(__half2*)(outh + (size_t)(row + 8) * 1024 + col) =
                    __floats2half2_rn(a2 + b0, a3 + b1);
            } else {
                float2 r0 = *(const float2*)(resid + (size_t)row * 1024 + col);
                float2 r1 = *(const float2*)(resid + (size_t)(row + 8) * 1024 + col);
                *(float2*)(outf + (size_t)row * 1024 + col) =
                    make_float2(a0 + b0 + r0.x, a1 + b1 + r0.y);
                *(float2*)(outf + (size_t)(row + 8) * 1024 + col) =
                    make_float2(a2 + b0 + r1.x, a3 + b1 + r1.y);
            }
        }
    }
}

__global__ void __launch_bounds__(256, 3) gemm_qkv_kernel(
    const float* __restrict__ bq, const float* __restrict__ bk,
    const float* __restrict__ bv) {
    int z = blockIdx.z;
    const __half* W = g_wh + (size_t)z * (H_ * H_);
    const float* bias = (z == 0) ? bq : (z == 1) ? bk : bv;
    __half* out = (z == 0) ? g_q : (z == 1) ? g_k : g_v;
    gemm_body<false>(g_xn, W, bias, out, nullptr, nullptr);
}

__global__ void __launch_bounds__(256, 3) gemm_wo_kernel(const float* __restrict__ bo) {
    gemm_body<true>(g_att, g_wh + (size_t)3 * H_ * H_, bo, nullptr, g_co, g_comm);
}

// ---------------- kernel 4: attention, mma.sync flash pattern --------------
// Block = (b, 4 heads), 128 threads; warp w handles head hq*4+w.
// PV uses fp16 accumulators -> ~96 regs -> 5 blocks/SM (20 warps).
__global__ void __launch_bounds__(128) attn_kernel() {
    const int blk = blockIdx.x;          // b*2 + hq
    const int b = blk >> 1, hq = blk & 1;
    const int tid = threadIdx.x;
    const int w = tid >> 5, lane = tid & 31;
    const int head = hq * 4 + w;

    __shared__ __align__(16) __half sq[4][16][136];
    __shared__ __align__(16) __half sk[4][16][136];
    __shared__ __align__(16) __half sv[4][16][136];

    const size_t base = (size_t)(b * 16) * 1024 + head * 128;

    // load q/k/v for this head: 16 rows x 128 halves = 256 uint4 chunks
    #pragma unroll
    for (int i = lane; i < 256; i += 32) {
        int r = i >> 4, c = (i & 15) * 8;
        *(uint4*)&sq[w][r][c] = *(const uint4*)(g_q + base + (size_t)r * 1024 + c);
        *(uint4*)&sk[w][r][c] = *(const uint4*)(g_k + base + (size_t)r * 1024 + c);
        *(uint4*)&sv[w][r][c] = *(const uint4*)(g_v + base + (size_t)r * 1024 + c);
    }
    __syncwarp();

    // ---- QK^T: scores 16x16 in acc0 (cols 0-7) + acc1 (cols 8-15) ----
    float acc0[4] = {0.f, 0.f, 0.f, 0.f};
    float acc1[4] = {0.f, 0.f, 0.f, 0.f};
    #pragma unroll
    for (int kc = 0; kc < 8; kc++) {
        uint32_t a[4];
        ldmatrix_x4(a, (uint32_t)__cvta_generic_to_shared(
            &sq[w][lane & 15][kc * 16 + ((lane >> 4) << 3)]));
        uint32_t tb[4];
        int mi = lane >> 3;
        ldmatrix_x4(tb, (uint32_t)__cvta_generic_to_shared(
            &sk[w][(mi & 1) * 8 + (lane & 7)][kc * 16 + ((mi >> 1) << 3)]));
        uint32_t b0[2] = {tb[0], tb[2]};
        uint32_t b1[2] = {tb[1], tb[3]};
        mma16816(acc0, a, b0);
        mma16816(acc1, a, b1);
    }

    // ---- softmax in registers ----
    const float scale = 0.0883883476483184f;   // 1/sqrt(128)
    float ga0 = acc0[0] * scale, ga1 = acc0[1] * scale;
    float ga2 = acc1[0] * scale, ga3 = acc1[1] * scale;
    float hb0 = acc0[2] * scale, hb1 = acc0[3] * scale;
    float hb2 = acc1[2] * scale, hb3 = acc1[3] * scale;

    float mxg = fmaxf(fmaxf(ga0, ga1), fmaxf(ga2, ga3));
    float mxh = fmaxf(fmaxf(hb0, hb1), fmaxf(hb2, hb3));
    #pragma unroll
    for (int o = 1; o < 4; o <<= 1) {
        mxg = fmaxf(mxg, __shfl_xor_sync(0xffffffffu, mxg, o, 4));
        mxh = fmaxf(mxh, __shfl_xor_sync(0xffffffffu, mxh, o, 4));
    }
    ga0 = expf(ga0 - mxg); ga1 = expf(ga1 - mxg);
    ga2 = expf(ga2 - mxg); ga3 = expf(ga3 - mxg);
    hb0 = expf(hb0 - mxh); hb1 = expf(hb1 - mxh);
    hb2 = expf(hb2 - mxh); hb3 = expf(hb3 - mxh);
    float sg = ga0 + ga1 + ga2 + ga3;
    float sh = hb0 + hb1 + hb2 + hb3;
    #pragma unroll
    for (int o = 1; o < 4; o <<= 1) {
        sg += __shfl_xor_sync(0xffffffffu, sg, o, 4);
        sh += __shfl_xor_sync(0xffffffffu, sh, o, 4);
    }
    float ig = 1.f / sg, ih = 1.f / sh;
    ga0 *= ig; ga1 *= ig; ga2 *= ig; ga3 *= ig;
    hb0 *= ih; hb1 *= ih; hb2 *= ih; hb3 *= ih;

    // ---- pack P into A-frag layout (m16k16): acc layout == A layout ----
    uint32_t pa[4];
    __half2 t01;
    t01 = __floats2half2_rn(ga0, ga1); pa[0] = *(uint32_t*)&t01;
    t01 = __floats2half2_rn(hb0, hb1); pa[1] = *(uint32_t*)&t01;
    t01 = __floats2half2_rn(ga2, ga3); pa[2] = *(uint32_t*)&t01;
    t01 = __floats2half2_rn(hb2, hb3); pa[3] = *(uint32_t*)&t01;

    // ---- P @ V: 16 n-tiles over 128 dims, fp16 accumulators ----
    uint32_t o[16][2];
    #pragma unroll
    for (int nt = 0; nt < 16; nt++) {
        o[nt][0] = 0u; o[nt][1] = 0u;
        uint32_t bv2[2];
        ldmatrix_x2_trans(bv2, (uint32_t)__cvta_generic_to_shared(
            &sv[w][lane & 15][nt * 8]));
        mma16816h(o[nt], pa, bv2);
    }

    // ---- stage O into sq[w] (accumulators already half2), then store ----
    const int g = lane >> 2, t4 = lane & 3;
    #pragma unroll
    for (int nt = 0; nt < 16; nt++) {
        *(uint32_t*)&sq[w][g][nt * 8 + 2 * t4]     = o[nt][0];
        *(uint32_t*)&sq[w][g + 8][nt * 8 + 2 * t4] = o[nt][1];
    }
    __syncwarp();
    #pragma unroll
    for (int i = lane; i < 256; i += 32) {
        int r = i >> 4, c = (i & 15) * 8;
        *(uint4*)(g_att + base + (size_t)r * 1024 + c) = *(uint4*)&sq[w][r][c];
    }
}

// ---------------- kernel 6: gate + final blend -----------------------------
__global__ void __launch_bounds__(256) gate_kernel(
    const float* __restrict__ x, const float* __restrict__ wg,
    const float* __restrict__ bg, float* __restrict__ out) {
    const int m = blockIdx.x;
    const int t = threadIdx.x;

    float4 xv = ((const float4*)(x + (size_t)m * H_))[t];
    float4 cv = ((const float4*)(g_co + (size_t)m * H_))[t];
    float4 w1 = ((const float4*)wg)[t];
    float4 w2 = ((const float4*)(wg + H_))[t];

    float s = xv.x * w1.x + xv.y * w1.y + xv.z * w1.z + xv.w * w1.w
            + cv.x * w2.x + cv.y * w2.y + cv.z * w2.z + cv.w * w2.w;

    __shared__ float red[8];
    #pragma unroll
    for (int o = 16; o; o >>= 1) s += __shfl_xor_sync(0xffffffffu, s, o);
    int w = t >> 5;
    if ((t & 31) == 0) red[w] = s;
    __syncthreads();
    if (t < 32) {
        s = (t < 8) ? red[t] : 0.f;
        #pragma unroll
        for (int o = 4; o; o >>= 1) s += __shfl_xor_sync(0xffffffffu, s, o);
        if (t == 0) red[0] = s;
    }
    __syncthreads();
    s = red[0];

    float g = 1.f / (1.f + expf(-(s + bg[0])));
    float4 o4;
    o4.x = g * cv.x + (1.f - g) * xv.x;
    o4.y = g * cv.y + (1.f - g) * xv.y;
    o4.z = g * cv.z + (1.f - g) * xv.z;
    o4.w = g * cv.w + (1.f - g) * xv.w;
    ((float4*)(out + (size_t)m * H_))[t] = o4;
}

// ---------------- launch ----------------------------------------------------
extern "C" void kernel_launch(void* const* d_in, const int* in_sizes, int n_in,
                              void* d_out, int out_size) {
    const float* x    = (const float*)d_in[0];
    const float* ln_g = (const float*)d_in[1];
    const float* ln_b = (const float*)d_in[2];
    const float* wq   = (const float*)d_in[3];
    const float* bq   = (const float*)d_in[4];
    const float* wk   = (const float*)d_in[5];
    const float* bk   = (const float*)d_in[6];
    const float* wv   = (const float*)d_in[7];
    const float* bv   = (const float*)d_in[8];
    const float* wo   = (const float*)d_in[9];
    const float* bo   = (const float*)d_in[10];
    const float* wg   = (const float*)d_in[11];
    const float* bg   = (const float*)d_in[12];
    float* out = (float*)d_out;

    static bool attr_done = false;
    if (!attr_done) {
        cudaFuncSetAttribute((const void*)gemm_qkv_kernel,
                             cudaFuncAttributeMaxDynamicSharedMemorySize, GEMM_SMEM);
        cudaFuncSetAttribute((const void*)gemm_wo_kernel,
                             cudaFuncAttributeMaxDynamicSharedMemorySize, GEMM_SMEM);
        attr_done = true;
    }

    wconv_kernel<<<4096, 256>>>(wq, wk, wv, wo);
    comm_ln_kernel<<<M_, 256>>>(x, ln_g, ln_b);
    gemm_qkv_kernel<<<dim3(8, 256, 3), 256, GEMM_SMEM>>>(bq, bk, bv);
    attn_kernel<<<B_ * 2, 128>>>();
    gemm_wo_kernel<<<dim3(8, 256, 1), 256, GEMM_SMEM>>>(bo);
    gate_kernel<<<M_, 256>>>(x, wg, bg, out);
}